// round 10
// baseline (speedup 1.0000x reference)
#include <cuda_runtime.h>

#define SDIM 1024
#define DDIM 64
#define BH   16
#define NF   4
#define R2   4   // rows per conv/softmax block

typedef unsigned long long ull;

// d = a*b + d on packed f32x2 (dual-rate fp32 path, PTX-only)
#define FMA2(d, a, b) asm("fma.rn.f32x2 %0, %1, %2, %0;" : "+l"(d) : "l"(a), "l"(b))
#define PACK_DUP(d, f) asm("mov.b64 %0, {%1, %1};" : "=l"(d) : "f"(f))
#define UNPACK2(lo, hi, v) asm("mov.b64 {%0, %1}, %2;" : "=f"(lo), "=f"(hi) : "l"(v))

// Scratch: dp scores and attention probabilities (64 MB each).
__device__ float g_dp[(size_t)BH * SDIM * SDIM];
__device__ float g_attn[(size_t)BH * SDIM * SDIM];

// ---------------------------------------------------------------------------
// K1: dp[bh][s][t] = (1/8) * sum_d Q[bh][s][d] * K[bh][t][d]
// 128(s)x64(t) tile, 256 threads, 8s x 4t per thread, f32x2 FMA.
// As transposed [d][s] so a-values load as packed s-pairs.
// ---------------------------------------------------------------------------
#define AS_STR 132   // 128 s + 4 pad (528B rows, 16B aligned)
#define BS_STR 68    // 64 t + 4 pad

__global__ __launch_bounds__(256) void qk_kernel(const float* __restrict__ Q,
                                                 const float* __restrict__ Km) {
    extern __shared__ float sm[];
    float* As = sm;                 // [64][AS_STR]  (d, s)
    float* Bs = sm + 64 * AS_STR;   // [64][BS_STR]  (d, t)
    const int tid = threadIdx.x;
    const int bh = blockIdx.z;
    const int s0 = blockIdx.y * 128, t0 = blockIdx.x * 64;
    const float* Qh = Q  + (size_t)bh * SDIM * DDIM;
    const float* Kh = Km + (size_t)bh * SDIM * DDIM;

    // A tile: 128 s x 64 d, scaled, stored transposed [d][s]
#pragma unroll
    for (int j = 0; j < 8; j++) {
        int i = tid + j * 256;
        int r = i >> 4, c4 = i & 15;
        float4 q = __ldg((const float4*)(Qh + (size_t)(s0 + r) * DDIM) + c4);
        int d = c4 * 4;
        As[(d + 0) * AS_STR + r] = q.x * 0.125f;
        As[(d + 1) * AS_STR + r] = q.y * 0.125f;
        As[(d + 2) * AS_STR + r] = q.z * 0.125f;
        As[(d + 3) * AS_STR + r] = q.w * 0.125f;
    }
    // B tile: 64 t x 64 d, stored transposed [d][t]
#pragma unroll
    for (int j = 0; j < 4; j++) {
        int i = tid + j * 256;
        int r = i >> 4, c4 = i & 15;
        float4 kv = __ldg((const float4*)(Kh + (size_t)(t0 + r) * DDIM) + c4);
        int d = c4 * 4;
        Bs[(d + 0) * BS_STR + r] = kv.x;
        Bs[(d + 1) * BS_STR + r] = kv.y;
        Bs[(d + 2) * BS_STR + r] = kv.z;
        Bs[(d + 3) * BS_STR + r] = kv.w;
    }
    __syncthreads();

    const int tx = tid & 15, ty = tid >> 4;
    const int c0 = tx * 4, r0 = ty * 8;

    ull acc[4][4];  // [t_j][s_pair]
#pragma unroll
    for (int j = 0; j < 4; j++)
#pragma unroll
        for (int p = 0; p < 4; p++) acc[j][p] = 0ull;

#pragma unroll 8
    for (int k = 0; k < 64; k++) {
        const ulonglong2* ap = (const ulonglong2*)(As + k * AS_STR + r0);
        ulonglong2 alo = ap[0];   // pairs (s0,s1),(s2,s3)
        ulonglong2 ahi = ap[1];   // pairs (s4,s5),(s6,s7)
        float4 b = *(const float4*)(Bs + k * BS_STR + c0);
        ull bd0, bd1, bd2, bd3;
        PACK_DUP(bd0, b.x); PACK_DUP(bd1, b.y);
        PACK_DUP(bd2, b.z); PACK_DUP(bd3, b.w);
        FMA2(acc[0][0], alo.x, bd0); FMA2(acc[0][1], alo.y, bd0);
        FMA2(acc[0][2], ahi.x, bd0); FMA2(acc[0][3], ahi.y, bd0);
        FMA2(acc[1][0], alo.x, bd1); FMA2(acc[1][1], alo.y, bd1);
        FMA2(acc[1][2], ahi.x, bd1); FMA2(acc[1][3], ahi.y, bd1);
        FMA2(acc[2][0], alo.x, bd2); FMA2(acc[2][1], alo.y, bd2);
        FMA2(acc[2][2], ahi.x, bd2); FMA2(acc[2][3], ahi.y, bd2);
        FMA2(acc[3][0], alo.x, bd3); FMA2(acc[3][1], alo.y, bd3);
        FMA2(acc[3][2], ahi.x, bd3); FMA2(acc[3][3], ahi.y, bd3);
    }

    // Unpack and store: rows s0+r0+i (i=0..7), cols t0+c0..+3
    float lo[4][4], hi[4][4];
#pragma unroll
    for (int j = 0; j < 4; j++)
#pragma unroll
        for (int p = 0; p < 4; p++) UNPACK2(lo[j][p], hi[j][p], acc[j][p]);

    float* out = g_dp + ((size_t)bh << 20);
#pragma unroll
    for (int i = 0; i < 8; i++) {
        int p = i >> 1;
        float4 o;
        if (i & 1) o = make_float4(hi[0][p], hi[1][p], hi[2][p], hi[3][p]);
        else       o = make_float4(lo[0][p], lo[1][p], lo[2][p], lo[3][p]);
        *(float4*)&out[(size_t)(s0 + r0 + i) * SDIM + t0 + c0] = o;
    }
}

// ---------------------------------------------------------------------------
// K2: fused conv(3x3,NF)+bias+leaky+linear+mask+softmax. R2 rows per block.
// ---------------------------------------------------------------------------
__global__ __launch_bounds__(256) void conv_softmax_kernel(
    const int* __restrict__ mask,
    const float* __restrict__ cw, const float* __restrict__ cb,
    const float* __restrict__ lw, const float* __restrict__ lb) {
    __shared__ float rows[R2 + 2][SDIM];
    __shared__ float red[9];
    const int tid = threadIdx.x;
    const int s0 = blockIdx.x * R2, bh = blockIdx.y;
    const float* dpb = g_dp + ((size_t)bh << 20);

#pragma unroll
    for (int j = 0; j < R2 + 2; j++) {
        int sr = s0 + j - 1;
        if (sr >= 0 && sr < SDIM) {
            const float4* src = (const float4*)(dpb + (size_t)sr * SDIM);
            ((float4*)rows[j])[tid] = __ldg(src + tid);
        } else {
            ((float4*)rows[j])[tid] = make_float4(0.f, 0.f, 0.f, 0.f);
        }
    }

    float w[NF][9], b_[NF], l_[NF];
#pragma unroll
    for (int f = 0; f < NF; f++) {
#pragma unroll
        for (int j = 0; j < 9; j++) w[f][j] = __ldg(&cw[f * 9 + j]);
        b_[f] = __ldg(&cb[f]);
        l_[f] = __ldg(&lw[f]);
    }
    const float lb0 = __ldg(lb);
    const int bb = bh >> 3;
    __syncthreads();

    for (int r = 0; r < R2; r++) {
        const int s = s0 + r;
        const int* mrow = mask + ((size_t)bb * SDIM + s) * SDIM;

        float x[4];
#pragma unroll
        for (int q = 0; q < 4; q++) {
            int t = tid + q * 256;
            float v[9];
#pragma unroll
            for (int di = 0; di < 3; di++) {
#pragma unroll
                for (int dj = 0; dj < 3; dj++) {
                    int tt = t + dj - 1;
                    v[di * 3 + dj] = (tt >= 0 && tt < SDIM) ? rows[r + di][tt] : 0.f;
                }
            }
            float pre = lb0;
#pragma unroll
            for (int f = 0; f < NF; f++) {
                float c = b_[f];
#pragma unroll
                for (int j = 0; j < 9; j++) c += w[f][j] * v[j];
                pre += l_[f] * fmaxf(c, 0.01f * c);
            }
            if (__ldg(&mrow[t]) == 0) pre = -1e30f;
            x[q] = pre;
        }

        float m = fmaxf(fmaxf(x[0], x[1]), fmaxf(x[2], x[3]));
#pragma unroll
        for (int off = 16; off; off >>= 1)
            m = fmaxf(m, __shfl_xor_sync(0xffffffffu, m, off));
        if ((tid & 31) == 0) red[tid >> 5] = m;
        __syncthreads();
        if (tid == 0) {
            float mm = red[0];
#pragma unroll
            for (int i = 1; i < 8; i++) mm = fmaxf(mm, red[i]);
            red[8] = mm;
        }
        __syncthreads();
        m = red[8];
        __syncthreads();

        float e[4], ssum = 0.f;
#pragma unroll
        for (int q = 0; q < 4; q++) { e[q] = __expf(x[q] - m); ssum += e[q]; }
#pragma unroll
        for (int off = 16; off; off >>= 1)
            ssum += __shfl_xor_sync(0xffffffffu, ssum, off);
        if ((tid & 31) == 0) red[tid >> 5] = ssum;
        __syncthreads();
        if (tid == 0) {
            float sm = red[0];
#pragma unroll
            for (int i = 1; i < 8; i++) sm += red[i];
            red[8] = sm;
        }
        __syncthreads();
        const float inv = 1.0f / red[8];
        __syncthreads();

        float* arow = g_attn + ((size_t)bh << 20) + (size_t)s * SDIM;
#pragma unroll
        for (int q = 0; q < 4; q++) arow[tid + q * 256] = e[q] * inv;
    }
}

// ---------------------------------------------------------------------------
// K3: out[bh][s][d] = sum_t attn[bh][s][t] * V[bh][t][d]
// 64(s)x64(d) tile, 128 threads, 8s x 4d per thread, f32x2, k-chunks of 64.
// attn chunk stored transposed [k][s]; V chunk natural [k][d].
// ---------------------------------------------------------------------------
__global__ __launch_bounds__(128) void av_kernel(const float* __restrict__ V,
                                                 float* __restrict__ out) {
    __shared__ float As[64 * BS_STR];  // [k][s] 64x68
    __shared__ float Bs[64 * BS_STR];  // [k][d] 64x68
    const int tid = threadIdx.x;
    const int bh = blockIdx.y;
    const int s0 = blockIdx.x * 64;
    const float* attn = g_attn + ((size_t)bh << 20);
    const float* Vh = V + (size_t)bh * SDIM * DDIM;
    const int tx = tid & 15, ty = tid >> 4;   // ty 0..7
    const int c0 = tx * 4, r0 = ty * 8;

    ull acc[4][4];  // [d_j][s_pair]
#pragma unroll
    for (int j = 0; j < 4; j++)
#pragma unroll
        for (int p = 0; p < 4; p++) acc[j][p] = 0ull;

    for (int k0 = 0; k0 < SDIM; k0 += 64) {
        // attn tile 64s x 64k -> As[k][s] (transposed)
#pragma unroll
        for (int j = 0; j < 8; j++) {
            int i = tid + j * 128;
            int r = i >> 4, c4 = i & 15;
            float4 a = __ldg((const float4*)(attn + (size_t)(s0 + r) * SDIM + k0) + c4);
            int k = c4 * 4;
            As[(k + 0) * BS_STR + r] = a.x;
            As[(k + 1) * BS_STR + r] = a.y;
            As[(k + 2) * BS_STR + r] = a.z;
            As[(k + 3) * BS_STR + r] = a.w;
        }
        // V tile 64k x 64d -> Bs[k][d] (natural)
#pragma unroll
        for (int j = 0; j < 8; j++) {
            int i = tid + j * 128;
            int r = i >> 4, c4 = i & 15;
            float4 v = __ldg((const float4*)(Vh + (size_t)(k0 + r) * DDIM) + c4);
            *(float4*)&Bs[r * BS_STR + c4 * 4] = v;
        }
        __syncthreads();

#pragma unroll 8
        for (int k = 0; k < 64; k++) {
            const ulonglong2* ap = (const ulonglong2*)(As + k * BS_STR + r0);
            ulonglong2 alo = ap[0];
            ulonglong2 ahi = ap[1];
            float4 b = *(const float4*)(Bs + k * BS_STR + c0);
            ull bd0, bd1, bd2, bd3;
            PACK_DUP(bd0, b.x); PACK_DUP(bd1, b.y);
            PACK_DUP(bd2, b.z); PACK_DUP(bd3, b.w);
            FMA2(acc[0][0], alo.x, bd0); FMA2(acc[0][1], alo.y, bd0);
            FMA2(acc[0][2], ahi.x, bd0); FMA2(acc[0][3], ahi.y, bd0);
            FMA2(acc[1][0], alo.x, bd1); FMA2(acc[1][1], alo.y, bd1);
            FMA2(acc[1][2], ahi.x, bd1); FMA2(acc[1][3], ahi.y, bd1);
            FMA2(acc[2][0], alo.x, bd2); FMA2(acc[2][1], alo.y, bd2);
            FMA2(acc[2][2], ahi.x, bd2); FMA2(acc[2][3], ahi.y, bd2);
            FMA2(acc[3][0], alo.x, bd3); FMA2(acc[3][1], alo.y, bd3);
            FMA2(acc[3][2], ahi.x, bd3); FMA2(acc[3][3], ahi.y, bd3);
        }
        __syncthreads();
    }

    float lo[4][4], hi[4][4];
#pragma unroll
    for (int j = 0; j < 4; j++)
#pragma unroll
        for (int p = 0; p < 4; p++) UNPACK2(lo[j][p], hi[j][p], acc[j][p]);

#pragma unroll
    for (int i = 0; i < 8; i++) {
        int p = i >> 1;
        float4 o;
        if (i & 1) o = make_float4(hi[0][p], hi[1][p], hi[2][p], hi[3][p]);
        else       o = make_float4(lo[0][p], lo[1][p], lo[2][p], lo[3][p]);
        *(float4*)&out[((size_t)bh * SDIM + s0 + r0 + i) * DDIM + c0] = o;
    }
}

extern "C" void kernel_launch(void* const* d_in, const int* in_sizes, int n_in,
                              void* d_out, int out_size) {
    const float* Q    = (const float*)d_in[0];
    const float* Kp   = (const float*)d_in[1];
    const float* V    = (const float*)d_in[2];
    const int*   mask = (const int*)d_in[3];
    const float* cw   = (const float*)d_in[4];
    const float* cb   = (const float*)d_in[5];
    const float* lw   = (const float*)d_in[6];
    const float* lb   = (const float*)d_in[7];
    float* out = (float*)d_out;

    const int qk_smem = (64 * AS_STR + 64 * BS_STR) * sizeof(float);  // 51200 B
    static bool attr_set = false;
    if (!attr_set) {
        cudaFuncSetAttribute(qk_kernel, cudaFuncAttributeMaxDynamicSharedMemorySize, qk_smem);
        attr_set = true;
    }

    dim3 g1(SDIM / 64, SDIM / 128, BH);
    qk_kernel<<<g1, 256, qk_smem>>>(Q, Kp);

    dim3 g2(SDIM / R2, BH);
    conv_softmax_kernel<<<g2, 256>>>(mask, cw, cb, lw, lb);

    dim3 g3(SDIM / 64, BH);
    av_kernel<<<g3, 128>>>(V, out);
}

// round 13
// speedup vs baseline: 1.1140x; 1.1140x over previous
#include <cuda_runtime.h>

#define SDIM 1024
#define DDIM 64
#define BH   16
#define NF   4
#define R2   4   // rows per conv/softmax block
#define KSPL 4   // k-splits for AV

typedef unsigned long long ull;

// d = a*b + d on packed f32x2
#define FMA2(d, a, b) asm("fma.rn.f32x2 %0, %1, %2, %0;" : "+l"(d) : "l"(a), "l"(b))
#define PACK_DUP(d, f) asm("mov.b64 %0, {%1, %1};" : "=l"(d) : "f"(f))
#define UNPACK2(lo, hi, v) asm("mov.b64 {%0, %1}, %2;" : "=f"(lo), "=f"(hi) : "l"(v))

// Scratch: dp scores / (later) AV partials, and attention probabilities.
__device__ float g_dp[(size_t)BH * SDIM * SDIM];    // 64 MB; reused as AV partials after K2
__device__ float g_attn[(size_t)BH * SDIM * SDIM];  // 64 MB

#define AS_STR 132   // 128 s + 4 pad
#define BS_STR 68    // 64 + 4 pad

// ---------------------------------------------------------------------------
// K1: dp = (1/8) Q K^T.  128(s)x64(t) tile, 256 thr, 8s x 4t, f32x2. (60.4us)
// ---------------------------------------------------------------------------
__global__ __launch_bounds__(256) void qk_kernel(const float* __restrict__ Q,
                                                 const float* __restrict__ Km) {
    extern __shared__ float sm[];
    float* As = sm;                 // [64][AS_STR]  (d, s)
    float* Bs = sm + 64 * AS_STR;   // [64][BS_STR]  (d, t)
    const int tid = threadIdx.x;
    const int bh = blockIdx.z;
    const int s0 = blockIdx.y * 128, t0 = blockIdx.x * 64;
    const float* Qh = Q  + (size_t)bh * SDIM * DDIM;
    const float* Kh = Km + (size_t)bh * SDIM * DDIM;

#pragma unroll
    for (int j = 0; j < 8; j++) {
        int i = tid + j * 256;
        int r = i >> 4, c4 = i & 15;
        float4 q = __ldg((const float4*)(Qh + (size_t)(s0 + r) * DDIM) + c4);
        int d = c4 * 4;
        As[(d + 0) * AS_STR + r] = q.x * 0.125f;
        As[(d + 1) * AS_STR + r] = q.y * 0.125f;
        As[(d + 2) * AS_STR + r] = q.z * 0.125f;
        As[(d + 3) * AS_STR + r] = q.w * 0.125f;
    }
#pragma unroll
    for (int j = 0; j < 4; j++) {
        int i = tid + j * 256;
        int r = i >> 4, c4 = i & 15;
        float4 kv = __ldg((const float4*)(Kh + (size_t)(t0 + r) * DDIM) + c4);
        int d = c4 * 4;
        Bs[(d + 0) * BS_STR + r] = kv.x;
        Bs[(d + 1) * BS_STR + r] = kv.y;
        Bs[(d + 2) * BS_STR + r] = kv.z;
        Bs[(d + 3) * BS_STR + r] = kv.w;
    }
    __syncthreads();

    const int tx = tid & 15, ty = tid >> 4;
    const int c0 = tx * 4, r0 = ty * 8;

    ull acc[4][4];
#pragma unroll
    for (int j = 0; j < 4; j++)
#pragma unroll
        for (int p = 0; p < 4; p++) acc[j][p] = 0ull;

#pragma unroll 8
    for (int k = 0; k < 64; k++) {
        const ulonglong2* ap = (const ulonglong2*)(As + k * AS_STR + r0);
        ulonglong2 alo = ap[0];
        ulonglong2 ahi = ap[1];
        float4 b = *(const float4*)(Bs + k * BS_STR + c0);
        ull bd0, bd1, bd2, bd3;
        PACK_DUP(bd0, b.x); PACK_DUP(bd1, b.y);
        PACK_DUP(bd2, b.z); PACK_DUP(bd3, b.w);
        FMA2(acc[0][0], alo.x, bd0); FMA2(acc[0][1], alo.y, bd0);
        FMA2(acc[0][2], ahi.x, bd0); FMA2(acc[0][3], ahi.y, bd0);
        FMA2(acc[1][0], alo.x, bd1); FMA2(acc[1][1], alo.y, bd1);
        FMA2(acc[1][2], ahi.x, bd1); FMA2(acc[1][3], ahi.y, bd1);
        FMA2(acc[2][0], alo.x, bd2); FMA2(acc[2][1], alo.y, bd2);
        FMA2(acc[2][2], ahi.x, bd2); FMA2(acc[2][3], ahi.y, bd2);
        FMA2(acc[3][0], alo.x, bd3); FMA2(acc[3][1], alo.y, bd3);
        FMA2(acc[3][2], ahi.x, bd3); FMA2(acc[3][3], ahi.y, bd3);
    }

    float lo[4][4], hi[4][4];
#pragma unroll
    for (int j = 0; j < 4; j++)
#pragma unroll
        for (int p = 0; p < 4; p++) UNPACK2(lo[j][p], hi[j][p], acc[j][p]);

    float* out = g_dp + ((size_t)bh << 20);
#pragma unroll
    for (int i = 0; i < 8; i++) {
        int p = i >> 1;
        float4 o;
        if (i & 1) o = make_float4(hi[0][p], hi[1][p], hi[2][p], hi[3][p]);
        else       o = make_float4(lo[0][p], lo[1][p], lo[2][p], lo[3][p]);
        *(float4*)&out[(size_t)(s0 + r0 + i) * SDIM + t0 + c0] = o;
    }
}

// ---------------------------------------------------------------------------
// K2: fused conv(3x3,NF)+bias+leaky+linear+mask+softmax. R2 rows per block.
// ---------------------------------------------------------------------------
__global__ __launch_bounds__(256) void conv_softmax_kernel(
    const int* __restrict__ mask,
    const float* __restrict__ cw, const float* __restrict__ cb,
    const float* __restrict__ lw, const float* __restrict__ lb) {
    __shared__ float rows[R2 + 2][SDIM];
    __shared__ float red[9];
    const int tid = threadIdx.x;
    const int s0 = blockIdx.x * R2, bh = blockIdx.y;
    const float* dpb = g_dp + ((size_t)bh << 20);

#pragma unroll
    for (int j = 0; j < R2 + 2; j++) {
        int sr = s0 + j - 1;
        if (sr >= 0 && sr < SDIM) {
            const float4* src = (const float4*)(dpb + (size_t)sr * SDIM);
            ((float4*)rows[j])[tid] = __ldg(src + tid);
        } else {
            ((float4*)rows[j])[tid] = make_float4(0.f, 0.f, 0.f, 0.f);
        }
    }

    float w[NF][9], b_[NF], l_[NF];
#pragma unroll
    for (int f = 0; f < NF; f++) {
#pragma unroll
        for (int j = 0; j < 9; j++) w[f][j] = __ldg(&cw[f * 9 + j]);
        b_[f] = __ldg(&cb[f]);
        l_[f] = __ldg(&lw[f]);
    }
    const float lb0 = __ldg(lb);
    const int bb = bh >> 3;
    __syncthreads();

    for (int r = 0; r < R2; r++) {
        const int s = s0 + r;
        const int* mrow = mask + ((size_t)bb * SDIM + s) * SDIM;

        float x[4];
#pragma unroll
        for (int q = 0; q < 4; q++) {
            int t = tid + q * 256;
            float v[9];
#pragma unroll
            for (int di = 0; di < 3; di++) {
#pragma unroll
                for (int dj = 0; dj < 3; dj++) {
                    int tt = t + dj - 1;
                    v[di * 3 + dj] = (tt >= 0 && tt < SDIM) ? rows[r + di][tt] : 0.f;
                }
            }
            float pre = lb0;
#pragma unroll
            for (int f = 0; f < NF; f++) {
                float c = b_[f];
#pragma unroll
                for (int j = 0; j < 9; j++) c += w[f][j] * v[j];
                pre += l_[f] * fmaxf(c, 0.01f * c);
            }
            if (__ldg(&mrow[t]) == 0) pre = -1e30f;
            x[q] = pre;
        }

        float m = fmaxf(fmaxf(x[0], x[1]), fmaxf(x[2], x[3]));
#pragma unroll
        for (int off = 16; off; off >>= 1)
            m = fmaxf(m, __shfl_xor_sync(0xffffffffu, m, off));
        if ((tid & 31) == 0) red[tid >> 5] = m;
        __syncthreads();
        if (tid == 0) {
            float mm = red[0];
#pragma unroll
            for (int i = 1; i < 8; i++) mm = fmaxf(mm, red[i]);
            red[8] = mm;
        }
        __syncthreads();
        m = red[8];
        __syncthreads();

        float e[4], ssum = 0.f;
#pragma unroll
        for (int q = 0; q < 4; q++) { e[q] = __expf(x[q] - m); ssum += e[q]; }
#pragma unroll
        for (int off = 16; off; off >>= 1)
            ssum += __shfl_xor_sync(0xffffffffu, ssum, off);
        if ((tid & 31) == 0) red[tid >> 5] = ssum;
        __syncthreads();
        if (tid == 0) {
            float sm = red[0];
#pragma unroll
            for (int i = 1; i < 8; i++) sm += red[i];
            red[8] = sm;
        }
        __syncthreads();
        const float inv = 1.0f / red[8];
        __syncthreads();

        float* arow = g_attn + ((size_t)bh << 20) + (size_t)s * SDIM;
#pragma unroll
        for (int q = 0; q < 4; q++) arow[tid + q * 256] = e[q] * inv;
    }
}

// ---------------------------------------------------------------------------
// K3a: AV partial GEMM, k-split. Each block: 64(s)x64(d) over a 256-wide
// k-range; grid 64x16 = 1024 blocks (~7/SM). Partials into g_dp (dead scratch).
// R8-proven inner loop: 256 thr, 4s x 4d, KC=64.
// ---------------------------------------------------------------------------
__global__ __launch_bounds__(256) void av_partial(const float* __restrict__ V) {
    __shared__ float As[64][68];  // attn tile [s][k]
    __shared__ float Bs[64][68];  // V tile    [k][d]
    const int tid = threadIdx.x;
    const int bh = blockIdx.y;
    const int st = blockIdx.x & 15, ks = blockIdx.x >> 4;
    const int s0 = st * 64;
    const int kbase = ks * (SDIM / KSPL);
    const float* attn = g_attn + ((size_t)bh << 20);
    const float* Vh = V + (size_t)bh * SDIM * DDIM;
    const int tx = tid & 15, ty = tid >> 4;
    const int r0 = ty * 4, c0 = tx * 4;

    float acc[4][4] = {};
    for (int kc = 0; kc < SDIM / KSPL; kc += 64) {
        const int k0 = kbase + kc;
#pragma unroll
        for (int j = 0; j < 4; j++) {   // attn tile 64x64
            int i = tid + j * 256;
            int r = i >> 4, c4 = i & 15;
            float4 a = __ldg((const float4*)(attn + (size_t)(s0 + r) * SDIM + k0) + c4);
            *(float4*)&As[r][c4 * 4] = a;
        }
#pragma unroll
        for (int j = 0; j < 4; j++) {   // V tile 64x64
            int i = tid + j * 256;
            int r = i >> 4, c4 = i & 15;
            float4 b = __ldg((const float4*)(Vh + (size_t)(k0 + r) * DDIM) + c4);
            *(float4*)&Bs[r][c4 * 4] = b;
        }
        __syncthreads();
#pragma unroll 16
        for (int k = 0; k < 64; k++) {
            float4 b = *(const float4*)&Bs[k][c0];
            float a0 = As[r0 + 0][k];
            float a1 = As[r0 + 1][k];
            float a2 = As[r0 + 2][k];
            float a3 = As[r0 + 3][k];
            acc[0][0] += a0 * b.x; acc[0][1] += a0 * b.y; acc[0][2] += a0 * b.z; acc[0][3] += a0 * b.w;
            acc[1][0] += a1 * b.x; acc[1][1] += a1 * b.y; acc[1][2] += a1 * b.z; acc[1][3] += a1 * b.w;
            acc[2][0] += a2 * b.x; acc[2][1] += a2 * b.y; acc[2][2] += a2 * b.z; acc[2][3] += a2 * b.w;
            acc[3][0] += a3 * b.x; acc[3][1] += a3 * b.y; acc[3][2] += a3 * b.z; acc[3][3] += a3 * b.w;
        }
        __syncthreads();
    }

    // partial[ks][bh][s][d] into g_dp
    float* pp = g_dp + (((size_t)ks * BH + bh) * SDIM + s0) * DDIM;
#pragma unroll
    for (int i = 0; i < 4; i++) {
        float4 v = make_float4(acc[i][0], acc[i][1], acc[i][2], acc[i][3]);
        *(float4*)&pp[(size_t)(r0 + i) * DDIM + c0] = v;
    }
}

// K3b: out = sum of KSPL partials (L2-resident, ~3us).
__global__ __launch_bounds__(256) void av_reduce(float* __restrict__ out) {
    const size_t i = (size_t)blockIdx.x * 256 + threadIdx.x;  // float4 index
    const size_t chunk = (size_t)BH * SDIM * DDIM / 4;        // 262144 float4s
    const float4* p = (const float4*)g_dp;
    float4 a = p[i];
#pragma unroll
    for (int k = 1; k < KSPL; k++) {
        float4 b = p[k * chunk + i];
        a.x += b.x; a.y += b.y; a.z += b.z; a.w += b.w;
    }
    ((float4*)out)[i] = a;
}

extern "C" void kernel_launch(void* const* d_in, const int* in_sizes, int n_in,
                              void* d_out, int out_size) {
    const float* Q    = (const float*)d_in[0];
    const float* Kp   = (const float*)d_in[1];
    const float* V    = (const float*)d_in[2];
    const int*   mask = (const int*)d_in[3];
    const float* cw   = (const float*)d_in[4];
    const float* cb   = (const float*)d_in[5];
    const float* lw   = (const float*)d_in[6];
    const float* lb   = (const float*)d_in[7];
    float* out = (float*)d_out;

    const int qk_smem = (64 * AS_STR + 64 * BS_STR) * sizeof(float);  // 51200 B
    static bool attr_set = false;
    if (!attr_set) {
        cudaFuncSetAttribute(qk_kernel, cudaFuncAttributeMaxDynamicSharedMemorySize, qk_smem);
        attr_set = true;
    }

    dim3 g1(SDIM / 64, SDIM / 128, BH);
    qk_kernel<<<g1, 256, qk_smem>>>(Q, Kp);

    dim3 g2(SDIM / R2, BH);
    conv_softmax_kernel<<<g2, 256>>>(mask, cw, cb, lw, lb);

    dim3 g3((SDIM / 64) * KSPL, BH);
    av_partial<<<g3, 256>>>(V);

    av_reduce<<<(BH * SDIM * DDIM / 4) / 256, 256>>>(out);
}